// round 16
// baseline (speedup 1.0000x reference)
#include <cuda_runtime.h>
#include <cuda_fp16.h>
#include <math.h>
#include <stdint.h>

// ---------------- problem constants ----------------
#define N_ROWS 16384
#define D2     1024
#define KSYM   8192
#define BM     128            // rows per CTA (blockIdx.y)
#define BN     128            // symbol cols per CTA (blockIdx.x)
#define BK     64             // k per stage (two 32-k sub-chunks)
#define NCHUNK (D2 / BK)      // 16
#define RECORDS 64            // per-row top2 records = 64 col tiles (warpN merged in-CTA)
#define MARGIN 1.5f
#define MAXCAND 24

// output packing (reference tuple order, flattened, float32)
#define ZQ_OFF   0ULL
#define LOSS_OFF 16777216ULL
#define MIDX_OFF 16777217ULL
#define NCB_OFF  16793601ULL
#define NCS_OFF  25182209ULL
#define NEA_OFF  25190401ULL

// smem stage layout: two fp16 segments, 128 rows x 128B each (parity-swizzled halves)
#define SEG_Z   0
#define SEG_CB  16384
#define STAGE   32768
#define NSTAGE  3
#define SMEM_BYTES (NSTAGE * STAGE)   // 98304 -> 2 CTAs/SM

// ---------------- scratch (device globals, no allocation) ----------------
__device__ float  g_cnorm[KSYM];
__device__ float  g_top2v[(size_t)N_ROWS * RECORDS * 2];
__device__ int    g_top2i[(size_t)N_ROWS * RECORDS * 2];
__device__ int    g_counts[KSYM];
__device__ double g_loss;
__device__ float  g_cs[KSYM];
// pair-permuted fp16 operand copies (uint32 = 2 elems), 512 words/row
__device__ uint32_t g_zp[(size_t)N_ROWS * 512];
__device__ uint32_t g_cbp[(size_t)KSYM * 512];

// ---------------- helpers ----------------
__device__ __forceinline__ uint32_t smem_to_u32(const void* p) {
    uint32_t a;
    asm("{ .reg .u64 t; cvta.to.shared.u64 t, %1; cvt.u32.u64 %0, t; }" : "=r"(a) : "l"(p));
    return a;
}
__device__ __forceinline__ void cp16(uint32_t dst, const void* src) {
    asm volatile("cp.async.cg.shared.global [%0], [%1], 16;" :: "r"(dst), "l"(src));
}
__device__ __forceinline__ uint4 lds128(uint32_t addr) {
    uint4 v;
    asm volatile("ld.shared.v4.b32 {%0,%1,%2,%3}, [%4];"
        : "=r"(v.x), "=r"(v.y), "=r"(v.z), "=r"(v.w) : "r"(addr));
    return v;
}
__device__ __forceinline__ void mma_f16(float* d, const uint32_t* a, const uint32_t* b) {
    asm volatile(
        "mma.sync.aligned.m16n8k16.row.col.f32.f16.f16.f32 "
        "{%0,%1,%2,%3}, {%4,%5,%6,%7}, {%8,%9}, {%0,%1,%2,%3};"
        : "+f"(d[0]), "+f"(d[1]), "+f"(d[2]), "+f"(d[3])
        : "r"(a[0]), "r"(a[1]), "r"(a[2]), "r"(a[3]), "r"(b[0]), "r"(b[1]));
}
// pair p -> chunk c=p>>4 (32-k granule), pp=p&15, slot c*16 + (pp&3)*4 + (pp>>2)
__device__ __forceinline__ int pslot(int p) {
    int c = p >> 4, pp = p & 15;
    return c * 16 + (pp & 3) * 4 + (pp >> 2);
}

// ---------------- 0a. z permute ----------------
__global__ void perm_z_kernel(const float* __restrict__ zr, const float* __restrict__ zi) {
    size_t total = (size_t)N_ROWS * 512;
    size_t stride = (size_t)gridDim.x * blockDim.x;
    for (size_t i = (size_t)blockIdx.x * blockDim.x + threadIdx.x; i < total; i += stride) {
        int n = (int)(i >> 9), p = (int)(i & 511);
        int k = 2 * p;
        float a, b;
        if (k < 512) { a = zr[(size_t)n * 512 + k]; b = zr[(size_t)n * 512 + k + 1]; }
        else         { a = zi[(size_t)n * 512 + k - 512]; b = zi[(size_t)n * 512 + k - 511]; }
        __half2 h = __floats2half2_rn(a, b);
        uint32_t pack; *(__half2*)&pack = h;
        g_zp[(size_t)n * 512 + pslot(p)] = pack;
    }
}

// ---------------- 0b. codebook permute + row norm (fused) ----------------
__global__ void perm_cb_norm_kernel(const float* __restrict__ cb) {
    const int row = blockIdx.x;
    const int tid = threadIdx.x;   // 256 threads; each handles one float4 = pairs 2t, 2t+1
    const float* src = cb + (size_t)row * D2;
    float4 v = *(const float4*)(src + tid * 4);

    __half2 h0 = __floats2half2_rn(v.x, v.y);
    __half2 h1 = __floats2half2_rn(v.z, v.w);
    uint32_t p0, p1;
    *(__half2*)&p0 = h0; *(__half2*)&p1 = h1;
    g_cbp[(size_t)row * 512 + pslot(2 * tid)]     = p0;
    g_cbp[(size_t)row * 512 + pslot(2 * tid + 1)] = p1;

    double s = (double)v.x * v.x + (double)v.y * v.y + (double)v.z * v.z + (double)v.w * v.w;
    __shared__ double sh[256];
    sh[tid] = s; __syncthreads();
    for (int o = 128; o > 0; o >>= 1) { if (tid < o) sh[tid] += sh[tid + o]; __syncthreads(); }
    if (tid == 0) g_cnorm[row] = (float)sh[0];
}

// ---------------- 3. fused dot-GEMM score kernel (fp16; 32 warps/SM) ----------------
// 512 threads, 16 warps: warp grid 4(M) x 4(N), warp tile 32x32, CTA tile 128x128.
// Also folds init: NEA = 0.99*embed_avg slice, counts/loss zero (DRAM idle otherwise).
__global__ __launch_bounds__(512, 2)
void score_mma_kernel(const float* __restrict__ embed_avg, float* __restrict__ out) {
    extern __shared__ char smem[];
    const uint32_t sbu = smem_to_u32(smem);
    const int tid   = threadIdx.x;
    const int wid   = tid >> 5;
    const int lane  = tid & 31;
    const int g     = lane >> 2;
    const int tig   = lane & 3;
    const int warpM = wid >> 2;       // 0..3 (32 rows)
    const int warpN = wid & 3;        // 0..3 (32 cols)
    const int rowBase = blockIdx.y * BM;
    const int cbase   = blockIdx.x * BN;

    // ---- stage loader: 4 x 16B per thread (2 segs x 2 quad-slots), parity-swizzled ----
    auto load_stage = [&](int c, int buf) {
        const uint32_t bb = sbu + (uint32_t)buf * STAGE;
#pragma unroll
        for (int i = 0; i < 2; i++) {
            int qi = tid + (i << 9);
            int r = qi >> 3, qq = qi & 7;
            int sc = qq >> 2, q4 = qq & 3;
            uint32_t so = (uint32_t)(r * 128 + (((uint32_t)(sc * 64)) ^ ((uint32_t)((r & 1) << 6))) + q4 * 16);
            size_t gw = (size_t)(2 * c + sc) * 16 + q4 * 4;
            cp16(bb + SEG_Z + so, g_zp + (size_t)(rowBase + r) * 512 + gw);
            cp16(bb + SEG_CB + so, g_cbp + (size_t)(cbase + r) * 512 + gw);
        }
        asm volatile("cp.async.commit_group;" ::: "memory");
    };

    load_stage(0, 0);
    load_stage(1, 1);

    // ---- folded init (overlaps with cp.async prologue); NEA_OFF is odd -> scalar stores ----
    {
        int cta = blockIdx.y * gridDim.x + blockIdx.x;   // 0..8191
        if (tid < 256) {
            size_t i = (size_t)cta * 1024 + tid * 4;
            float4 v = *(const float4*)(embed_avg + i);
            float* dst = out + NEA_OFF + i;
            dst[0] = 0.99f * v.x;
            dst[1] = 0.99f * v.y;
            dst[2] = 0.99f * v.z;
            dst[3] = 0.99f * v.w;
        } else if (tid == 256) {
            g_counts[cta] = 0;
            if (cta == 0) g_loss = 0.0;
        }
    }

    float accd[2][4][4];
#pragma unroll
    for (int mt = 0; mt < 2; mt++)
#pragma unroll
        for (int nt = 0; nt < 4; nt++)
#pragma unroll
            for (int e = 0; e < 4; e++) accd[mt][nt][e] = 0.f;

    const uint32_t gx = (uint32_t)((g & 1) << 6);
    const uint32_t aZbase = SEG_Z  + (uint32_t)(warpM * 32 + g) * 128 + tig * 16;
    const uint32_t aBbase = SEG_CB + (uint32_t)(warpN * 32 + g) * 128 + tig * 16;

    int buf = 0;
    for (int c = 0; c < NCHUNK; ++c) {
        if (c + 1 < NCHUNK) asm volatile("cp.async.wait_group 1;" ::: "memory");
        else                asm volatile("cp.async.wait_group 0;" ::: "memory");
        __syncthreads();
        if (c + 2 < NCHUNK) {
            int nb = buf + 2; if (nb >= NSTAGE) nb -= NSTAGE;
            load_stage(c + 2, nb);
        }
        const uint32_t bb = sbu + (uint32_t)buf * STAGE;

#pragma unroll
        for (int sc = 0; sc < 2; sc++) {
            const uint32_t o = ((uint32_t)(sc * 64)) ^ gx;
            uint32_t ax[4][4];
#pragma unroll
            for (int s = 0; s < 4; s++) {
                uint4 vz = lds128(bb + aZbase + (uint32_t)(s * 1024) + o);
                ax[s][0] = vz.x; ax[s][1] = vz.y; ax[s][2] = vz.z; ax[s][3] = vz.w;
            }
#pragma unroll
            for (int nt = 0; nt < 4; nt++) {
                uint4 vb = lds128(bb + aBbase + (uint32_t)(nt * 1024) + o);
                uint32_t bw[4] = {vb.x, vb.y, vb.z, vb.w};
#pragma unroll
                for (int t = 0; t < 2; t++) {
                    uint32_t af0[4] = {ax[0][2*t], ax[1][2*t], ax[0][2*t+1], ax[1][2*t+1]};
                    uint32_t af1[4] = {ax[2][2*t], ax[3][2*t], ax[2][2*t+1], ax[3][2*t+1]};
                    uint32_t bf2[2] = {bw[2*t], bw[2*t+1]};
                    mma_f16(accd[0][nt], af0, bf2);
                    mma_f16(accd[1][nt], af1, bf2);
                }
            }
        }
        buf++; if (buf >= NSTAGE) buf = 0;
    }

    // ---- epilogue: approx score + per-row top-2, 4 warpN merged via smem ----
    const float INF = __int_as_float(0x7f800000);
    float rV1[2][2], rV2[2][2];
    int   rI1[2][2], rI2[2][2];
#pragma unroll
    for (int mt = 0; mt < 2; mt++)
#pragma unroll
        for (int hi = 0; hi < 2; hi++) {
            float V1 = INF, V2 = INF;
            int   I1 = 0x7fffffff, I2 = 0x7fffffff;
#pragma unroll
            for (int nt = 0; nt < 4; nt++)
#pragma unroll
                for (int e = 0; e < 2; e++) {
                    int col = cbase + warpN * 32 + nt * 8 + 2 * tig + e;
                    float s = fmaf(-2.f, accd[mt][nt][hi * 2 + e], g_cnorm[col]);
                    if (s < V1 || (s == V1 && col < I1)) { V2 = V1; I2 = I1; V1 = s; I1 = col; }
                    else if (s < V2 || (s == V2 && col < I2)) { V2 = s; I2 = col; }
                }
#pragma unroll
            for (int off = 1; off <= 2; off <<= 1) {
                float ov1 = __shfl_xor_sync(0xffffffffu, V1, off);
                int   oi1 = __shfl_xor_sync(0xffffffffu, I1, off);
                float ov2 = __shfl_xor_sync(0xffffffffu, V2, off);
                int   oi2 = __shfl_xor_sync(0xffffffffu, I2, off);
                if (ov1 < V1 || (ov1 == V1 && oi1 < I1)) {
                    float nv2; int ni2;
                    if (V1 < ov2 || (V1 == ov2 && I1 < oi2)) { nv2 = V1; ni2 = I1; }
                    else { nv2 = ov2; ni2 = oi2; }
                    V1 = ov1; I1 = oi1; V2 = nv2; I2 = ni2;
                } else if (ov1 < V2 || (ov1 == V2 && oi1 < I2)) {
                    V2 = ov1; I2 = oi1;
                }
            }
            rV1[mt][hi] = V1; rI1[mt][hi] = I1;
            rV2[mt][hi] = V2; rI2[mt][hi] = I2;
        }

    // smem handoff: warpN 1..3 publish, warpN 0 merges + writes global
    float* sv = (float*)smem;            // [3][128][2]
    int*   si = (int*)(smem + 3072);     // [3][128][2]
    __syncthreads();   // stage buffers dead
    if (warpN != 0 && tig == 0) {
#pragma unroll
        for (int mt = 0; mt < 2; mt++)
#pragma unroll
            for (int hi = 0; hi < 2; hi++) {
                int rl = warpM * 32 + mt * 16 + hi * 8 + g;
                int bi = (warpN - 1) * 256 + rl * 2;
                sv[bi]     = rV1[mt][hi]; si[bi]     = rI1[mt][hi];
                sv[bi + 1] = rV2[mt][hi]; si[bi + 1] = rI2[mt][hi];
            }
    }
    __syncthreads();
    if (warpN == 0 && tig == 0) {
#pragma unroll
        for (int mt = 0; mt < 2; mt++)
#pragma unroll
            for (int hi = 0; hi < 2; hi++) {
                int rl = warpM * 32 + mt * 16 + hi * 8 + g;
                float V1 = rV1[mt][hi], V2 = rV2[mt][hi];
                int   I1 = rI1[mt][hi], I2 = rI2[mt][hi];
#pragma unroll
                for (int q = 0; q < 3; q++)
#pragma unroll
                    for (int e = 0; e < 2; e++) {
                        float ov = sv[q * 256 + rl * 2 + e];
                        int   oi = si[q * 256 + rl * 2 + e];
                        if (ov < V1 || (ov == V1 && oi < I1)) { V2 = V1; I2 = I1; V1 = ov; I1 = oi; }
                        else if (ov < V2 || (ov == V2 && oi < I2)) { V2 = ov; I2 = oi; }
                    }
                size_t o = ((size_t)(rowBase + rl) * RECORDS + blockIdx.x) * 2;
                g_top2v[o] = V1;  g_top2i[o] = I1;
                g_top2v[o + 1] = V2; g_top2i[o + 1] = I2;
            }
    }
}

// ---------------- 4. merge + fp64 refine + fused scatter (z_q, NEA, loss) ----------------
__global__ void merge_refine_scatter_kernel(
        const float* __restrict__ z_real,  const float* __restrict__ z_imag,
        const float* __restrict__ ctx_real, const float* __restrict__ ctx_imag,
        const int*   __restrict__ prev_idx,
        const float* __restrict__ codebook, const float* __restrict__ adjacency,
        const float* __restrict__ gate_w,   const float* __restrict__ gate_b,
        float* __restrict__ out) {
    __shared__ int s_cand[8][MAXCAND];
    __shared__ int s_cnt[8];
    const int w = threadIdx.x >> 5;
    const int lane = threadIdx.x & 31;
    const int n = blockIdx.x * 8 + w;
    const float INF = __int_as_float(0x7f800000);

    if (lane == 0) s_cnt[w] = 0;
    __syncwarp();

    // pass 1: approx min
    float v1 = INF; int i1 = 0x7fffffff;
    const size_t base = (size_t)n * (RECORDS * 2);
#pragma unroll
    for (int q = 0; q < 4; q++) {
        int e = lane + q * 32;
        float v = g_top2v[base + e];
        int ix  = g_top2i[base + e];
        if (v < v1 || (v == v1 && ix < i1)) { v1 = v; i1 = ix; }
    }
#pragma unroll
    for (int off = 16; off; off >>= 1) {
        float ov = __shfl_down_sync(0xffffffffu, v1, off);
        int   oi = __shfl_down_sync(0xffffffffu, i1, off);
        if (ov < v1 || (ov == v1 && oi < i1)) { v1 = ov; i1 = oi; }
    }
    float bv1 = __shfl_sync(0xffffffffu, v1, 0);
    int   bi1 = __shfl_sync(0xffffffffu, i1, 0);

    // pass 2: candidates within margin (true argmin provably inside)
    float thr = bv1 + MARGIN;
#pragma unroll
    for (int q = 0; q < 4; q++) {
        int e = lane + q * 32;
        float v = g_top2v[base + e];
        int ix  = g_top2i[base + e];
        if (v <= thr && ix != 0x7fffffff) {
            int pos = atomicAdd(&s_cnt[w], 1);
            if (pos < MAXCAND) s_cand[w][pos] = ix;
        }
    }
    __syncwarp();
    int count = s_cnt[w];
    if (count > MAXCAND) count = MAXCAND;

    int pick = bi1;
    if (count > 1) {
        double bestS = 1e300; int bestI = 0x7fffffff;
        const int p = prev_idx[n];
        for (int ci = 0; ci < count; ci++) {
            const int cc = s_cand[w][ci];
            double a0 = 0, a1 = 0, a2 = 0;
            for (int t = lane; t < D2; t += 32) {
                double zt = (t < 512) ? (double)z_real[(size_t)n * 512 + t]
                                      : (double)z_imag[(size_t)n * 512 + t - 512];
                double xt = (t < 512) ? (double)ctx_real[(size_t)n * 512 + t]
                                      : (double)ctx_imag[(size_t)n * 512 + t - 512];
                double cb = (double)codebook[(size_t)cc * D2 + t];
                double wv = (double)gate_w[(size_t)cc * D2 + t];
                a0 += cb * cb; a1 += zt * cb; a2 += xt * wv;
            }
            for (int o = 16; o; o >>= 1) {
                a0 += __shfl_down_sync(0xffffffffu, a0, o);
                a1 += __shfl_down_sync(0xffffffffu, a1, o);
                a2 += __shfl_down_sync(0xffffffffu, a2, o);
            }
            if (lane == 0) {
                double ad = (double)adjacency[(size_t)p * KSYM + cc];
                double gb = (double)gate_b[cc];
                double s = a0 - 2.0 * a1
                         - 0.8 * (1.0 / (1.0 + exp(-ad))) * (1.0 + 0.5 * tanh(a2 + gb));
                if (s < bestS || (s == bestS && cc < bestI)) { bestS = s; bestI = cc; }
            }
        }
        if (lane == 0) pick = bestI;
        pick = __shfl_sync(0xffffffffu, pick, 0);
    }
    if (lane == 0) {
        out[MIDX_OFF + n] = (float)pick;
        atomicAdd(&g_counts[pick], 1);
    }

    // ---- fused scatter: z_q gather, NEA atomics, loss ----
    float lsum = 0.f;
#pragma unroll
    for (int q = 0; q < 8; q++) {
        int d0 = (lane + q * 32) * 4;
        float4 c = *(const float4*)(codebook + (size_t)pick * D2 + d0);
        float4 z;
        if (d0 < 512) z = *(const float4*)(z_real + (size_t)n * 512 + d0);
        else          z = *(const float4*)(z_imag + (size_t)n * 512 + d0 - 512);

        *(float4*)(out + ZQ_OFF + (size_t)n * D2 + d0) = c;

        float* ea = out + NEA_OFF + (size_t)pick * D2 + d0;
        atomicAdd(ea + 0, 0.01f * z.x);
        atomicAdd(ea + 1, 0.01f * z.y);
        atomicAdd(ea + 2, 0.01f * z.z);
        atomicAdd(ea + 3, 0.01f * z.w);

        float dx = c.x - z.x, dy = c.y - z.y, dz = c.z - z.z, dw = c.w - z.w;
        lsum += dx * dx + dy * dy + dz * dz + dw * dw;
    }
    for (int o = 16; o; o >>= 1) lsum += __shfl_down_sync(0xffffffffu, lsum, o);
    if (lane == 0) atomicAdd(&g_loss, (double)lsum);
}

// ---------------- 6a. cluster-size EMA, cs, loss ----------------
__global__ void finalize_a_kernel(const float* __restrict__ cluster_size, float* __restrict__ out) {
    const int tid = threadIdx.x;  // 1024 threads
    float ncs[8];
    float psum = 0.f;
#pragma unroll
    for (int q = 0; q < 8; q++) {
        int k = tid * 8 + q;
        float v = cluster_size[k] * 0.99f + 0.01f * (float)g_counts[k];
        ncs[q] = v;
        out[NCS_OFF + k] = v;
        psum += v;
    }
    __shared__ float sh[1024];
    sh[tid] = psum; __syncthreads();
    for (int o = 512; o > 0; o >>= 1) { if (tid < o) sh[tid] += sh[tid + o]; __syncthreads(); }
    float ntot = sh[0];
#pragma unroll
    for (int q = 0; q < 8; q++) {
        float cs = (ncs[q] + 1e-6f) / (ntot + (float)KSYM * 1e-6f) * ntot;
        g_cs[tid * 8 + q] = cs;
    }
    if (tid == 0) out[LOSS_OFF] = (float)(1.25 * g_loss / 16777216.0);
}

// ---------------- 6b. new_codebook = new_embed_avg / cs ----------------
__global__ void finalize_b_kernel(float* __restrict__ out) {
    size_t total = (size_t)KSYM * D2;
    size_t stride = (size_t)gridDim.x * blockDim.x;
    for (size_t i = (size_t)blockIdx.x * blockDim.x + threadIdx.x; i < total; i += stride) {
        int k = (int)(i >> 10);
        out[NCB_OFF + i] = out[NEA_OFF + i] / g_cs[k];
    }
}

// ---------------- entry ----------------
extern "C" void kernel_launch(void* const* d_in, const int* in_sizes, int n_in,
                              void* d_out, int out_size) {
    const float* z_real     = (const float*)d_in[0];
    const float* z_imag     = (const float*)d_in[1];
    const float* ctx_real   = (const float*)d_in[2];
    const float* ctx_imag   = (const float*)d_in[3];
    const int*   prev_idx   = (const int*)d_in[4];
    const float* codebook   = (const float*)d_in[5];
    const float* adjacency  = (const float*)d_in[6];
    const float* gate_w     = (const float*)d_in[7];
    const float* gate_b     = (const float*)d_in[8];
    const float* cluster_sz = (const float*)d_in[9];
    const float* embed_avg  = (const float*)d_in[10];
    float* out = (float*)d_out;

    cudaFuncSetAttribute(score_mma_kernel, cudaFuncAttributeMaxDynamicSharedMemorySize, SMEM_BYTES);

    perm_z_kernel<<<4096, 256>>>(z_real, z_imag);
    perm_cb_norm_kernel<<<KSYM, 256>>>(codebook);
    // blockIdx.x = column tile (fast) so codebook stays L2-resident
    score_mma_kernel<<<dim3(KSYM / BN, N_ROWS / BM), 512, SMEM_BYTES>>>(embed_avg, out);
    merge_refine_scatter_kernel<<<N_ROWS / 8, 256>>>(z_real, z_imag, ctx_real, ctx_imag,
                                                     prev_idx, codebook, adjacency, gate_w, gate_b, out);
    finalize_a_kernel<<<1, 1024>>>(cluster_sz, out);
    finalize_b_kernel<<<8192, 256>>>(out);
}

// round 17
// speedup vs baseline: 1.8087x; 1.8087x over previous
#include <cuda_runtime.h>
#include <cuda_fp16.h>
#include <math.h>
#include <stdint.h>

// ---------------- problem constants ----------------
#define N_ROWS 16384
#define D2     1024
#define KSYM   8192
#define BM     128            // rows per CTA (blockIdx.y)
#define BN     128            // symbol cols per CTA (blockIdx.x)
#define BK     64             // k per stage (two 32-k sub-chunks)
#define NCHUNK (D2 / BK)      // 16
#define RECORDS 64            // per-row top2 records = 64 col tiles (warpN merged in-CTA)
#define MARGIN 1.5f
#define MAXCAND 24

// output packing (reference tuple order, flattened, float32)
#define ZQ_OFF   0ULL
#define LOSS_OFF 16777216ULL
#define MIDX_OFF 16777217ULL
#define NCB_OFF  16793601ULL
#define NCS_OFF  25182209ULL
#define NEA_OFF  25190401ULL

// smem stage layout: two fp16 segments, 128 rows x 128B each (parity-swizzled halves)
#define SEG_Z   0
#define SEG_CB  16384
#define STAGE   32768
#define NSTAGE  3
#define SMEM_BYTES (NSTAGE * STAGE)   // 98304 -> 2 CTAs/SM

// ---------------- scratch (device globals, no allocation) ----------------
__device__ float  g_cnorm[KSYM];
__device__ float  g_top2v[(size_t)N_ROWS * RECORDS * 2];
__device__ int    g_top2i[(size_t)N_ROWS * RECORDS * 2];
__device__ int    g_counts[KSYM];
__device__ double g_loss;
__device__ float  g_cs[KSYM];
// pair-permuted fp16 operand copies (uint32 = 2 elems), 512 words/row
__device__ uint32_t g_zp[(size_t)N_ROWS * 512];
__device__ uint32_t g_cbp[(size_t)KSYM * 512];

// ---------------- helpers ----------------
__device__ __forceinline__ uint32_t smem_to_u32(const void* p) {
    uint32_t a;
    asm("{ .reg .u64 t; cvta.to.shared.u64 t, %1; cvt.u32.u64 %0, t; }" : "=r"(a) : "l"(p));
    return a;
}
__device__ __forceinline__ void cp16(uint32_t dst, const void* src) {
    asm volatile("cp.async.cg.shared.global [%0], [%1], 16;" :: "r"(dst), "l"(src));
}
__device__ __forceinline__ uint4 lds128(uint32_t addr) {
    uint4 v;
    asm volatile("ld.shared.v4.b32 {%0,%1,%2,%3}, [%4];"
        : "=r"(v.x), "=r"(v.y), "=r"(v.z), "=r"(v.w) : "r"(addr));
    return v;
}
__device__ __forceinline__ void mma_f16(float* d, const uint32_t* a, const uint32_t* b) {
    asm volatile(
        "mma.sync.aligned.m16n8k16.row.col.f32.f16.f16.f32 "
        "{%0,%1,%2,%3}, {%4,%5,%6,%7}, {%8,%9}, {%0,%1,%2,%3};"
        : "+f"(d[0]), "+f"(d[1]), "+f"(d[2]), "+f"(d[3])
        : "r"(a[0]), "r"(a[1]), "r"(a[2]), "r"(a[3]), "r"(b[0]), "r"(b[1]));
}
// pair p -> chunk c=p>>4 (32-k granule), pp=p&15, slot c*16 + (pp&3)*4 + (pp>>2)
__device__ __forceinline__ int pslot(int p) {
    int c = p >> 4, pp = p & 15;
    return c * 16 + (pp & 3) * 4 + (pp >> 2);
}

// ---------------- 0a. z permute ----------------
__global__ void perm_z_kernel(const float* __restrict__ zr, const float* __restrict__ zi) {
    size_t total = (size_t)N_ROWS * 512;
    size_t stride = (size_t)gridDim.x * blockDim.x;
    for (size_t i = (size_t)blockIdx.x * blockDim.x + threadIdx.x; i < total; i += stride) {
        int n = (int)(i >> 9), p = (int)(i & 511);
        int k = 2 * p;
        float a, b;
        if (k < 512) { a = zr[(size_t)n * 512 + k]; b = zr[(size_t)n * 512 + k + 1]; }
        else         { a = zi[(size_t)n * 512 + k - 512]; b = zi[(size_t)n * 512 + k - 511]; }
        __half2 h = __floats2half2_rn(a, b);
        uint32_t pack; *(__half2*)&pack = h;
        g_zp[(size_t)n * 512 + pslot(p)] = pack;
    }
}

// ---------------- 0b. codebook permute + row norm (fused) ----------------
__global__ void perm_cb_norm_kernel(const float* __restrict__ cb) {
    const int row = blockIdx.x;
    const int tid = threadIdx.x;   // 256 threads; each handles one float4 = pairs 2t, 2t+1
    const float* src = cb + (size_t)row * D2;
    float4 v = *(const float4*)(src + tid * 4);

    __half2 h0 = __floats2half2_rn(v.x, v.y);
    __half2 h1 = __floats2half2_rn(v.z, v.w);
    uint32_t p0, p1;
    *(__half2*)&p0 = h0; *(__half2*)&p1 = h1;
    g_cbp[(size_t)row * 512 + pslot(2 * tid)]     = p0;
    g_cbp[(size_t)row * 512 + pslot(2 * tid + 1)] = p1;

    double s = (double)v.x * v.x + (double)v.y * v.y + (double)v.z * v.z + (double)v.w * v.w;
    __shared__ double sh[256];
    sh[tid] = s; __syncthreads();
    for (int o = 128; o > 0; o >>= 1) { if (tid < o) sh[tid] += sh[tid + o]; __syncthreads(); }
    if (tid == 0) g_cnorm[row] = (float)sh[0];
}

// ---------------- 3. fused dot-GEMM score kernel (fp16; R14 config + folded init) ----------------
// 256 threads, 8 warps: warp grid 4(M) x 2(N), warp tile 32x64, CTA tile 128x128, 2 CTAs/SM.
__global__ __launch_bounds__(256, 2)
void score_mma_kernel(const float* __restrict__ embed_avg, float* __restrict__ out) {
    extern __shared__ char smem[];
    const uint32_t sbu = smem_to_u32(smem);
    const int tid   = threadIdx.x;
    const int wid   = tid >> 5;
    const int lane  = tid & 31;
    const int g     = lane >> 2;
    const int tig   = lane & 3;
    const int warpM = wid >> 1;       // 0..3 (32 rows)
    const int warpN = wid & 1;        // 0..1 (64 cols)
    const int rowBase = blockIdx.y * BM;
    const int cbase   = blockIdx.x * BN;

    // ---- stage loader: 8 x 16B per thread (2 segs x 4 quads), parity-swizzled ----
    auto load_stage = [&](int c, int buf) {
        const uint32_t bb = sbu + (uint32_t)buf * STAGE;
#pragma unroll
        for (int i = 0; i < 4; i++) {
            int qi = tid + (i << 8);
            int r = qi >> 3, qq = qi & 7;
            int sc = qq >> 2, q4 = qq & 3;
            uint32_t so = (uint32_t)(r * 128 + (((uint32_t)(sc * 64)) ^ ((uint32_t)((r & 1) << 6))) + q4 * 16);
            size_t gw = (size_t)(2 * c + sc) * 16 + q4 * 4;
            cp16(bb + SEG_Z + so, g_zp + (size_t)(rowBase + r) * 512 + gw);
            cp16(bb + SEG_CB + so, g_cbp + (size_t)(cbase + r) * 512 + gw);
        }
        asm volatile("cp.async.commit_group;" ::: "memory");
    };

    load_stage(0, 0);
    load_stage(1, 1);

    // ---- folded init (overlaps cp.async prologue); NEA_OFF odd -> scalar stores ----
    {
        int cta = blockIdx.y * gridDim.x + blockIdx.x;   // 0..8191
        size_t i = (size_t)cta * 1024 + tid * 4;
        float4 v = *(const float4*)(embed_avg + i);
        float* dst = out + NEA_OFF + i;
        dst[0] = 0.99f * v.x;
        dst[1] = 0.99f * v.y;
        dst[2] = 0.99f * v.z;
        dst[3] = 0.99f * v.w;
        if (tid == 0) {
            g_counts[cta] = 0;
            if (cta == 0) g_loss = 0.0;
        }
    }

    float accd[2][8][4];
#pragma unroll
    for (int mt = 0; mt < 2; mt++)
#pragma unroll
        for (int nt = 0; nt < 8; nt++)
#pragma unroll
            for (int e = 0; e < 4; e++) accd[mt][nt][e] = 0.f;

    const uint32_t gx = (uint32_t)((g & 1) << 6);
    uint32_t aZ[4], aB[8];
#pragma unroll
    for (int s = 0; s < 4; s++)
        aZ[s] = SEG_Z + (uint32_t)(warpM * 32 + g + 8 * s) * 128 + tig * 16;
#pragma unroll
    for (int s = 0; s < 8; s++)
        aB[s] = SEG_CB + (uint32_t)(warpN * 64 + g + 8 * s) * 128 + tig * 16;

    int buf = 0;
    for (int c = 0; c < NCHUNK; ++c) {
        if (c + 1 < NCHUNK) asm volatile("cp.async.wait_group 1;" ::: "memory");
        else                asm volatile("cp.async.wait_group 0;" ::: "memory");
        __syncthreads();
        if (c + 2 < NCHUNK) {
            int nb = buf + 2; if (nb >= NSTAGE) nb -= NSTAGE;
            load_stage(c + 2, nb);
        }
        const uint32_t bb = sbu + (uint32_t)buf * STAGE;

#pragma unroll
        for (int sc = 0; sc < 2; sc++) {
            const uint32_t o = ((uint32_t)(sc * 64)) ^ gx;
            uint32_t ax[4][4];
#pragma unroll
            for (int s = 0; s < 4; s++) {
                uint4 vz = lds128(bb + aZ[s] + o);
                ax[s][0] = vz.x; ax[s][1] = vz.y; ax[s][2] = vz.z; ax[s][3] = vz.w;
            }
            uint32_t af0[2][4], af1[2][4];
#pragma unroll
            for (int t = 0; t < 2; t++) {
                af0[t][0] = ax[0][2*t]; af0[t][1] = ax[1][2*t];
                af0[t][2] = ax[0][2*t+1]; af0[t][3] = ax[1][2*t+1];
                af1[t][0] = ax[2][2*t]; af1[t][1] = ax[3][2*t];
                af1[t][2] = ax[2][2*t+1]; af1[t][3] = ax[3][2*t+1];
            }
#pragma unroll
            for (int nt = 0; nt < 8; nt++) {
                uint4 vb = lds128(bb + aB[nt] + o);
                uint32_t bw[4] = {vb.x, vb.y, vb.z, vb.w};
#pragma unroll
                for (int t = 0; t < 2; t++) {
                    uint32_t bf2[2] = {bw[2*t], bw[2*t+1]};
                    mma_f16(accd[0][nt], af0[t], bf2);
                    mma_f16(accd[1][nt], af1[t], bf2);
                }
            }
        }
        buf++; if (buf >= NSTAGE) buf = 0;
    }

    // ---- epilogue: approx score + per-row top-2, warpN pair merged via smem ----
    const float INF = __int_as_float(0x7f800000);
    float rV1[2][2], rV2[2][2];
    int   rI1[2][2], rI2[2][2];
#pragma unroll
    for (int mt = 0; mt < 2; mt++)
#pragma unroll
        for (int hi = 0; hi < 2; hi++) {
            float V1 = INF, V2 = INF;
            int   I1 = 0x7fffffff, I2 = 0x7fffffff;
#pragma unroll
            for (int nt = 0; nt < 8; nt++)
#pragma unroll
                for (int e = 0; e < 2; e++) {
                    int col = cbase + warpN * 64 + nt * 8 + 2 * tig + e;
                    float s = fmaf(-2.f, accd[mt][nt][hi * 2 + e], g_cnorm[col]);
                    if (s < V1 || (s == V1 && col < I1)) { V2 = V1; I2 = I1; V1 = s; I1 = col; }
                    else if (s < V2 || (s == V2 && col < I2)) { V2 = s; I2 = col; }
                }
#pragma unroll
            for (int off = 1; off <= 2; off <<= 1) {
                float ov1 = __shfl_xor_sync(0xffffffffu, V1, off);
                int   oi1 = __shfl_xor_sync(0xffffffffu, I1, off);
                float ov2 = __shfl_xor_sync(0xffffffffu, V2, off);
                int   oi2 = __shfl_xor_sync(0xffffffffu, I2, off);
                if (ov1 < V1 || (ov1 == V1 && oi1 < I1)) {
                    float nv2; int ni2;
                    if (V1 < ov2 || (V1 == ov2 && I1 < oi2)) { nv2 = V1; ni2 = I1; }
                    else { nv2 = ov2; ni2 = oi2; }
                    V1 = ov1; I1 = oi1; V2 = nv2; I2 = ni2;
                } else if (ov1 < V2 || (ov1 == V2 && oi1 < I2)) {
                    V2 = ov1; I2 = oi1;
                }
            }
            rV1[mt][hi] = V1; rI1[mt][hi] = I1;
            rV2[mt][hi] = V2; rI2[mt][hi] = I2;
        }

    // smem handoff: warpN==1 publishes, warpN==0 merges + writes global
    float* sv = (float*)smem;           // [128][2]
    int*   si = (int*)(smem + 1024);    // [128][2]
    __syncthreads();   // stage buffers dead
    if (warpN == 1 && tig == 0) {
#pragma unroll
        for (int mt = 0; mt < 2; mt++)
#pragma unroll
            for (int hi = 0; hi < 2; hi++) {
                int rl = warpM * 32 + mt * 16 + hi * 8 + g;
                sv[rl * 2]     = rV1[mt][hi]; si[rl * 2]     = rI1[mt][hi];
                sv[rl * 2 + 1] = rV2[mt][hi]; si[rl * 2 + 1] = rI2[mt][hi];
            }
    }
    __syncthreads();
    if (warpN == 0 && tig == 0) {
#pragma unroll
        for (int mt = 0; mt < 2; mt++)
#pragma unroll
            for (int hi = 0; hi < 2; hi++) {
                int rl = warpM * 32 + mt * 16 + hi * 8 + g;
                float V1 = rV1[mt][hi], V2 = rV2[mt][hi];
                int   I1 = rI1[mt][hi], I2 = rI2[mt][hi];
#pragma unroll
                for (int e = 0; e < 2; e++) {
                    float ov = sv[rl * 2 + e];
                    int   oi = si[rl * 2 + e];
                    if (ov < V1 || (ov == V1 && oi < I1)) { V2 = V1; I2 = I1; V1 = ov; I1 = oi; }
                    else if (ov < V2 || (ov == V2 && oi < I2)) { V2 = ov; I2 = oi; }
                }
                size_t o = ((size_t)(rowBase + rl) * RECORDS + blockIdx.x) * 2;
                g_top2v[o] = V1;  g_top2i[o] = I1;
                g_top2v[o + 1] = V2; g_top2i[o + 1] = I2;
            }
    }
}

// ---------------- 4. merge + fp64 refine + fused scatter (z_q, NEA, loss) ----------------
__global__ void merge_refine_scatter_kernel(
        const float* __restrict__ z_real,  const float* __restrict__ z_imag,
        const float* __restrict__ ctx_real, const float* __restrict__ ctx_imag,
        const int*   __restrict__ prev_idx,
        const float* __restrict__ codebook, const float* __restrict__ adjacency,
        const float* __restrict__ gate_w,   const float* __restrict__ gate_b,
        float* __restrict__ out) {
    __shared__ int s_cand[8][MAXCAND];
    __shared__ int s_cnt[8];
    const int w = threadIdx.x >> 5;
    const int lane = threadIdx.x & 31;
    const int n = blockIdx.x * 8 + w;
    const float INF = __int_as_float(0x7f800000);

    if (lane == 0) s_cnt[w] = 0;
    __syncwarp();

    // pass 1: approx min
    float v1 = INF; int i1 = 0x7fffffff;
    const size_t base = (size_t)n * (RECORDS * 2);
#pragma unroll
    for (int q = 0; q < 4; q++) {
        int e = lane + q * 32;
        float v = g_top2v[base + e];
        int ix  = g_top2i[base + e];
        if (v < v1 || (v == v1 && ix < i1)) { v1 = v; i1 = ix; }
    }
#pragma unroll
    for (int off = 16; off; off >>= 1) {
        float ov = __shfl_down_sync(0xffffffffu, v1, off);
        int   oi = __shfl_down_sync(0xffffffffu, i1, off);
        if (ov < v1 || (ov == v1 && oi < i1)) { v1 = ov; i1 = oi; }
    }
    float bv1 = __shfl_sync(0xffffffffu, v1, 0);
    int   bi1 = __shfl_sync(0xffffffffu, i1, 0);

    // pass 2: candidates within margin (true argmin provably inside)
    float thr = bv1 + MARGIN;
#pragma unroll
    for (int q = 0; q < 4; q++) {
        int e = lane + q * 32;
        float v = g_top2v[base + e];
        int ix  = g_top2i[base + e];
        if (v <= thr && ix != 0x7fffffff) {
            int pos = atomicAdd(&s_cnt[w], 1);
            if (pos < MAXCAND) s_cand[w][pos] = ix;
        }
    }
    __syncwarp();
    int count = s_cnt[w];
    if (count > MAXCAND) count = MAXCAND;

    int pick = bi1;
    if (count > 1) {
        double bestS = 1e300; int bestI = 0x7fffffff;
        const int p = prev_idx[n];
        for (int ci = 0; ci < count; ci++) {
            const int cc = s_cand[w][ci];
            double a0 = 0, a1 = 0, a2 = 0;
            for (int t = lane; t < D2; t += 32) {
                double zt = (t < 512) ? (double)z_real[(size_t)n * 512 + t]
                                      : (double)z_imag[(size_t)n * 512 + t - 512];
                double xt = (t < 512) ? (double)ctx_real[(size_t)n * 512 + t]
                                      : (double)ctx_imag[(size_t)n * 512 + t - 512];
                double cb = (double)codebook[(size_t)cc * D2 + t];
                double wv = (double)gate_w[(size_t)cc * D2 + t];
                a0 += cb * cb; a1 += zt * cb; a2 += xt * wv;
            }
            for (int o = 16; o; o >>= 1) {
                a0 += __shfl_down_sync(0xffffffffu, a0, o);
                a1 += __shfl_down_sync(0xffffffffu, a1, o);
                a2 += __shfl_down_sync(0xffffffffu, a2, o);
            }
            if (lane == 0) {
                double ad = (double)adjacency[(size_t)p * KSYM + cc];
                double gb = (double)gate_b[cc];
                double s = a0 - 2.0 * a1
                         - 0.8 * (1.0 / (1.0 + exp(-ad))) * (1.0 + 0.5 * tanh(a2 + gb));
                if (s < bestS || (s == bestS && cc < bestI)) { bestS = s; bestI = cc; }
            }
        }
        if (lane == 0) pick = bestI;
        pick = __shfl_sync(0xffffffffu, pick, 0);
    }
    if (lane == 0) {
        out[MIDX_OFF + n] = (float)pick;
        atomicAdd(&g_counts[pick], 1);
    }

    // ---- fused scatter: z_q gather, NEA atomics, loss ----
    float lsum = 0.f;
#pragma unroll
    for (int q = 0; q < 8; q++) {
        int d0 = (lane + q * 32) * 4;
        float4 c = *(const float4*)(codebook + (size_t)pick * D2 + d0);
        float4 z;
        if (d0 < 512) z = *(const float4*)(z_real + (size_t)n * 512 + d0);
        else          z = *(const float4*)(z_imag + (size_t)n * 512 + d0 - 512);

        *(float4*)(out + ZQ_OFF + (size_t)n * D2 + d0) = c;

        float* ea = out + NEA_OFF + (size_t)pick * D2 + d0;
        atomicAdd(ea + 0, 0.01f * z.x);
        atomicAdd(ea + 1, 0.01f * z.y);
        atomicAdd(ea + 2, 0.01f * z.z);
        atomicAdd(ea + 3, 0.01f * z.w);

        float dx = c.x - z.x, dy = c.y - z.y, dz = c.z - z.z, dw = c.w - z.w;
        lsum += dx * dx + dy * dy + dz * dz + dw * dw;
    }
    for (int o = 16; o; o >>= 1) lsum += __shfl_down_sync(0xffffffffu, lsum, o);
    if (lane == 0) atomicAdd(&g_loss, (double)lsum);
}

// ---------------- 6a. cluster-size EMA, cs, loss ----------------
__global__ void finalize_a_kernel(const float* __restrict__ cluster_size, float* __restrict__ out) {
    const int tid = threadIdx.x;  // 1024 threads
    float ncs[8];
    float psum = 0.f;
#pragma unroll
    for (int q = 0; q < 8; q++) {
        int k = tid * 8 + q;
        float v = cluster_size[k] * 0.99f + 0.01f * (float)g_counts[k];
        ncs[q] = v;
        out[NCS_OFF + k] = v;
        psum += v;
    }
    __shared__ float sh[1024];
    sh[tid] = psum; __syncthreads();
    for (int o = 512; o > 0; o >>= 1) { if (tid < o) sh[tid] += sh[tid + o]; __syncthreads(); }
    float ntot = sh[0];
#pragma unroll
    for (int q = 0; q < 8; q++) {
        float cs = (ncs[q] + 1e-6f) / (ntot + (float)KSYM * 1e-6f) * ntot;
        g_cs[tid * 8 + q] = cs;
    }
    if (tid == 0) out[LOSS_OFF] = (float)(1.25 * g_loss / 16777216.0);
}

// ---------------- 6b. new_codebook = new_embed_avg / cs ----------------
__global__ void finalize_b_kernel(float* __restrict__ out) {
    size_t total = (size_t)KSYM * D2;
    size_t stride = (size_t)gridDim.x * blockDim.x;
    for (size_t i = (size_t)blockIdx.x * blockDim.x + threadIdx.x; i < total; i += stride) {
        int k = (int)(i >> 10);
        out[NCB_OFF + i] = out[NEA_OFF + i] / g_cs[k];
    }
}

// ---------------- entry ----------------
extern "C" void kernel_launch(void* const* d_in, const int* in_sizes, int n_in,
                              void* d_out, int out_size) {
    const float* z_real     = (const float*)d_in[0];
    const float* z_imag     = (const float*)d_in[1];
    const float* ctx_real   = (const float*)d_in[2];
    const float* ctx_imag   = (const float*)d_in[3];
    const int*   prev_idx   = (const int*)d_in[4];
    const float* codebook   = (const float*)d_in[5];
    const float* adjacency  = (const float*)d_in[6];
    const float* gate_w     = (const float*)d_in[7];
    const float* gate_b     = (const float*)d_in[8];
    const float* cluster_sz = (const float*)d_in[9];
    const float* embed_avg  = (const float*)d_in[10];
    float* out = (float*)d_out;

    cudaFuncSetAttribute(score_mma_kernel, cudaFuncAttributeMaxDynamicSharedMemorySize, SMEM_BYTES);

    perm_z_kernel<<<4096, 256>>>(z_real, z_imag);
    perm_cb_norm_kernel<<<KSYM, 256>>>(codebook);
    // blockIdx.x = column tile (fast) so codebook stays L2-resident
    score_mma_kernel<<<dim3(KSYM / BN, N_ROWS / BM), 256, SMEM_BYTES>>>(embed_avg, out);
    merge_refine_scatter_kernel<<<N_ROWS / 8, 256>>>(z_real, z_imag, ctx_real, ctx_imag,
                                                     prev_idx, codebook, adjacency, gate_w, gate_b, out);
    finalize_a_kernel<<<1, 1024>>>(cluster_sz, out);
    finalize_b_kernel<<<8192, 256>>>(out);
}